// round 11
// baseline (speedup 1.0000x reference)
#include <cuda_runtime.h>
#include <cstdint>

// Fixed shapes: B=2048, L=200, D=128, A=64
#define DD 128
#define AA 64
#define LL 200
#define NEGINF (-4294967295.0f)
#define FNEGINF __int_as_float(0xff800000)

typedef unsigned long long ull;

__device__ __forceinline__ ull pk2(float lo, float hi) {
    ull r; asm("mov.b64 %0,{%1,%2};" : "=l"(r) : "f"(lo), "f"(hi)); return r;
}
__device__ __forceinline__ void upk2(ull v, float& lo, float& hi) {
    asm("mov.b64 {%0,%1},%2;" : "=f"(lo), "=f"(hi) : "l"(v));
}
__device__ __forceinline__ ull ffma2(ull a, ull b, ull c) {
    ull d; asm("fma.rn.f32x2 %0,%1,%2,%3;" : "=l"(d) : "l"(a), "l"(b), "l"(c)); return d;
}

// ---- kernel1 smem layout (float offsets) ----
#define F_KS   0          // K half [100][128], granule-XOR by (row>>1)&3   12800
#define F_WC   12800      // Wc [128][64] natural                            8192
#define F_W2   20992      // W2 [64][64] natural                             4096
#define F_QS   25088      // q[128]
#define F_QC   25216      // qc[64]  (16B aligned)
#define F_B2   25280      // b2[64]
#define F_W3   25344      // W3[64]
#define F_QCP  25408      // qc partials [8][64]
#define K1_FLOATS 25920
#define K1_BYTES (K1_FLOATS * 4)    // 103680 B -> 2 CTAs/SM

// =================== Kernel 1: scores for one (batch, l-half) ===================
extern "C" __global__ void __launch_bounds__(512, 2)
din_scores(const float* __restrict__ query,
           const float* __restrict__ keys,
           const int*   __restrict__ klen,
           const float* __restrict__ W1,
           const float* __restrict__ b1,
           const float* __restrict__ a1p,
           const float* __restrict__ W2,
           const float* __restrict__ b2,
           const float* __restrict__ a2p,
           const float* __restrict__ W3,
           const float* __restrict__ b3p,
           float* __restrict__ attp)     // raw masked scores out (B, L)
{
    extern __shared__ float sm[];
    float4* S4 = (float4*)sm;
    const int t    = threadIdx.x;
    const int bh   = blockIdx.x;
    const int b    = bh >> 1;
    const int rowbase = (bh & 1) * 100;
    const int lg   = t >> 3;               // 0..63
    const int cg   = t & 7;                // 0..7
    const int lane = t & 31;
    const int lgc  = (lg < 50) ? lg : 49;  // clamp so idle warps stay in-bounds
    const int l0   = 2 * lgc;
    const int cA   = 4 * cg;
    const int cB   = 32 + 4 * cg;

    const float pa1 = a1p[0], pa2 = a2p[0], b3v = b3p[0];
    const int   len = klen[b];

    // ---- Setup 1: q, W3, b2 ----
    if (t < DD) sm[F_QS + t] = query[b * DD + t];
    else if (t < DD + AA) sm[F_W3 + (t - DD)] = W3[t - DD];
    else if (t < DD + 2 * AA) sm[F_B2 + (t - DD - AA)] = b2[t - DD - AA];
    __syncthreads();

    // ---- Setup 2: Wc, W2, K-half copy, qc partials ----
    for (int i = t; i < DD * AA; i += 512) {
        int d = i >> 6, c = i & 63;
        sm[F_WC + i] = W1[(DD + d) * AA + c] - W1[(2 * DD + d) * AA + c]
                     + sm[F_QS + d] * W1[(3 * DD + d) * AA + c];
    }
    for (int i = t; i < AA * AA; i += 512) sm[F_W2 + i] = W2[i];
    {   // K rows rowbase..rowbase+99, float4, granule-XOR by (row>>1)&3
        const float4* K4 = (const float4*)(keys + ((size_t)b * LL + rowbase) * DD);
        for (int i = t; i < 100 * DD / 4; i += 512) {
            int row = i >> 5, q4 = i & 31;
            S4[row * 32 + (q4 ^ ((row >> 1) & 3))] = K4[i];
        }
    }
    {   // qc[a] = b1[a] + sum_d q[d]*(W1a+W1c)[d][a]
        int a = t & 63, seg = t >> 6;
        float s = 0.f;
        #pragma unroll
        for (int d = seg * 16; d < seg * 16 + 16; d++)
            s += sm[F_QS + d] * (W1[d * AA + a] + W1[(2 * DD + d) * AA + a]);
        sm[F_QCP + seg * 64 + a] = s;
    }
    __syncthreads();
    if (t < AA) {
        float s = b1[t];
        #pragma unroll
        for (int g = 0; g < 8; g++) s += sm[F_QCP + g * 64 + t];
        sm[F_QC + t] = s;
    }
    __syncthreads();

    // ==== GEMM1: 2l x 8c per thread, full d reduction ====
    ull acc[2][4];
    {
        const ull* qa = (const ull*)(sm + F_QC + cA);
        const ull* qb = (const ull*)(sm + F_QC + cB);
        acc[0][0] = qa[0]; acc[0][1] = qa[1]; acc[0][2] = qb[0]; acc[0][3] = qb[1];
        acc[1][0] = qa[0]; acc[1][1] = qa[1]; acc[1][2] = qb[0]; acc[1][3] = qb[1];
    }
    const int lp = lgc & 3;    // XOR key for rows l0, l0+1 (same key)
    #pragma unroll 1
    for (int d4 = 0; d4 < 32; d4++) {
        float4 kv0 = S4[l0 * 32 + (d4 ^ lp)];
        float4 kv1 = S4[(l0 + 1) * 32 + (d4 ^ lp)];
        #pragma unroll
        for (int dd = 0; dd < 4; dd++) {
            const float* wrow = sm + F_WC + (d4 * 4 + dd) * 64;
            ulonglong2 wa = *(const ulonglong2*)(wrow + cA);
            ulonglong2 wb = *(const ulonglong2*)(wrow + cB);
            float kd0 = (dd == 0) ? kv0.x : (dd == 1) ? kv0.y : (dd == 2) ? kv0.z : kv0.w;
            float kd1 = (dd == 0) ? kv1.x : (dd == 1) ? kv1.y : (dd == 2) ? kv1.z : kv1.w;
            ull k0 = pk2(kd0, kd0), k1 = pk2(kd1, kd1);
            acc[0][0] = ffma2(k0, wa.x, acc[0][0]);
            acc[0][1] = ffma2(k0, wa.y, acc[0][1]);
            acc[0][2] = ffma2(k0, wb.x, acc[0][2]);
            acc[0][3] = ffma2(k0, wb.y, acc[0][3]);
            acc[1][0] = ffma2(k1, wa.x, acc[1][0]);
            acc[1][1] = ffma2(k1, wa.y, acc[1][1]);
            acc[1][2] = ffma2(k1, wb.x, acc[1][2]);
            acc[1][3] = ffma2(k1, wb.y, acc[1][3]);
        }
    }
    // prelu(a1) -> hv[li][j]: j 0..3 = cA+j, j 4..7 = cB+(j-4)
    float hv[2][8];
    #pragma unroll
    for (int li = 0; li < 2; li++) {
        #pragma unroll
        for (int p = 0; p < 4; p++) {
            float lo, hi; upk2(acc[li][p], lo, hi);
            hv[li][2 * p]     = (lo >= 0.f) ? lo : pa1 * lo;
            hv[li][2 * p + 1] = (hi >= 0.f) ? hi : pa1 * hi;
        }
    }

    // ==== GEMM2 via warp shuffle: h1 stays in registers ====
    ull acc2[2][4];
    {
        const ull* ba = (const ull*)(sm + F_B2 + cA);
        const ull* bb = (const ull*)(sm + F_B2 + cB);
        acc2[0][0] = ba[0]; acc2[0][1] = ba[1]; acc2[0][2] = bb[0]; acc2[0][3] = bb[1];
        acc2[1][0] = ba[0]; acc2[1][1] = ba[1]; acc2[1][2] = bb[0]; acc2[1][3] = bb[1];
    }
    #pragma unroll
    for (int j = 0; j < 8; j++) {
        float v0 = hv[0][j], v1 = hv[1][j];
        #pragma unroll
        for (int cgp = 0; cgp < 8; cgp++) {
            int src = (lane & 24) | cgp;
            float h0 = __shfl_sync(0xffffffffu, v0, src, 32);
            float h1 = __shfl_sync(0xffffffffu, v1, src, 32);
            int a = (j < 4) ? (4 * cgp + j) : (28 + 4 * cgp + j);  // 32+4cgp+(j-4)
            const float* wrow = sm + F_W2 + a * 64;
            ulonglong2 wa = *(const ulonglong2*)(wrow + cA);
            ulonglong2 wb = *(const ulonglong2*)(wrow + cB);
            ull k0 = pk2(h0, h0), k1 = pk2(h1, h1);
            acc2[0][0] = ffma2(k0, wa.x, acc2[0][0]);
            acc2[0][1] = ffma2(k0, wa.y, acc2[0][1]);
            acc2[0][2] = ffma2(k0, wb.x, acc2[0][2]);
            acc2[0][3] = ffma2(k0, wb.y, acc2[0][3]);
            acc2[1][0] = ffma2(k1, wa.x, acc2[1][0]);
            acc2[1][1] = ffma2(k1, wa.y, acc2[1][1]);
            acc2[1][2] = ffma2(k1, wb.x, acc2[1][2]);
            acc2[1][3] = ffma2(k1, wb.y, acc2[1][3]);
        }
    }

    // prelu(a2) + W3 dot -> 2 partial scores, reduce over cg lanes
    float w3a[4], w3b[4];
    #pragma unroll
    for (int p = 0; p < 4; p++) { w3a[p] = sm[F_W3 + cA + p]; w3b[p] = sm[F_W3 + cB + p]; }
    float s0 = 0.f, s1 = 0.f;
    #pragma unroll
    for (int li = 0; li < 2; li++) {
        float s = 0.f, lo, hi;
        upk2(acc2[li][0], lo, hi);
        lo = (lo >= 0.f) ? lo : pa2 * lo;  hi = (hi >= 0.f) ? hi : pa2 * hi;
        s += lo * w3a[0] + hi * w3a[1];
        upk2(acc2[li][1], lo, hi);
        lo = (lo >= 0.f) ? lo : pa2 * lo;  hi = (hi >= 0.f) ? hi : pa2 * hi;
        s += lo * w3a[2] + hi * w3a[3];
        upk2(acc2[li][2], lo, hi);
        lo = (lo >= 0.f) ? lo : pa2 * lo;  hi = (hi >= 0.f) ? hi : pa2 * hi;
        s += lo * w3b[0] + hi * w3b[1];
        upk2(acc2[li][3], lo, hi);
        lo = (lo >= 0.f) ? lo : pa2 * lo;  hi = (hi >= 0.f) ? hi : pa2 * hi;
        s += lo * w3b[2] + hi * w3b[3];
        if (li == 0) s0 = s; else s1 = s;
    }
    #pragma unroll
    for (int o = 4; o > 0; o >>= 1) {
        s0 += __shfl_xor_sync(0xffffffffu, s0, o);
        s1 += __shfl_xor_sync(0xffffffffu, s1, o);
    }
    if (lg < 50 && cg == 0) {
        int l = rowbase + l0;
        attp[(size_t)b * LL + l]     = (l < len)     ? (s0 + b3v) : NEGINF;
        attp[(size_t)b * LL + l + 1] = (l + 1 < len) ? (s1 + b3v) : NEGINF;
    }
}

// =================== Kernel 2: softmax + out = att @ K ===================
extern "C" __global__ void __launch_bounds__(256)
din_softmax_out(const float* __restrict__ keys,
                float* __restrict__ outp,
                float* __restrict__ attp)
{
    __shared__ float sc[256];
    __shared__ float red[32];
    __shared__ float part[256];
    const int t = threadIdx.x;
    const int b = blockIdx.x;
    const int lane = t & 31, w = t >> 5;

    sc[t] = (t < LL) ? attp[(size_t)b * LL + t] : FNEGINF;
    __syncthreads();

    float v = sc[t];
    float m = v;
    #pragma unroll
    for (int o = 16; o > 0; o >>= 1) m = fmaxf(m, __shfl_xor_sync(0xffffffffu, m, o));
    if (lane == 0) red[w] = m;
    __syncthreads();
    if (t == 0) {
        float mm = red[0];
        for (int i = 1; i < 8; i++) mm = fmaxf(mm, red[i]);
        red[8] = mm;
    }
    __syncthreads();
    float M = red[8];
    float e = (t < LL) ? __expf(v - M) : 0.f;
    float ss = e;
    #pragma unroll
    for (int o = 16; o > 0; o >>= 1) ss += __shfl_xor_sync(0xffffffffu, ss, o);
    if (lane == 0) red[16 + w] = ss;
    __syncthreads();
    if (t == 0) {
        float s = 0.f;
        for (int i = 0; i < 8; i++) s += red[16 + i];
        red[24] = s;
    }
    __syncthreads();
    float at = 0.f;
    if (t < LL) {
        at = e / red[24];
        attp[(size_t)b * LL + t] = at;
    }
    __syncthreads();      // everyone done reading sc as scores
    sc[t] = at;           // now att (0 for pads)
    __syncthreads();

    // out[b][d] = sum_l att[l] * K[l][d]; 2-way l split, coalesced LDG
    {
        int d = t & 127, seg = t >> 7;
        const float* Kb = keys + ((size_t)b * LL + seg * 100) * DD + d;
        const float* Ap = sc + seg * 100;
        float a0 = 0.f, a1 = 0.f;
        #pragma unroll 4
        for (int l = 0; l < 100; l += 2) {
            a0 += Ap[l]     * Kb[l * DD];
            a1 += Ap[l + 1] * Kb[(l + 1) * DD];
        }
        part[t] = a0 + a1;
    }
    __syncthreads();
    if (t < DD) outp[(size_t)b * DD + t] = part[t] + part[t + 128];
}

extern "C" void kernel_launch(void* const* d_in, const int* in_sizes, int n_in,
                              void* d_out, int out_size) {
    const float* query = (const float*)d_in[0];
    const float* keys  = (const float*)d_in[1];
    const int*   klen  = (const int*)  d_in[2];
    const float* W1    = (const float*)d_in[3];
    const float* b1    = (const float*)d_in[4];
    const float* a1    = (const float*)d_in[5];
    const float* W2    = (const float*)d_in[6];
    const float* b2    = (const float*)d_in[7];
    const float* a2    = (const float*)d_in[8];
    const float* W3    = (const float*)d_in[9];
    const float* b3    = (const float*)d_in[10];

    int Bn = in_sizes[0] / DD;  // 2048
    float* outp = (float*)d_out;               // (B, D)
    float* attp = outp + (size_t)Bn * DD;      // (B, L)

    cudaFuncSetAttribute(din_scores,
                         cudaFuncAttributeMaxDynamicSharedMemorySize, K1_BYTES);
    din_scores<<<2 * Bn, 512, K1_BYTES>>>(
        query, keys, klen, W1, b1, a1, W2, b2, a2, W3, b3, attp);
    din_softmax_out<<<Bn, 256>>>(keys, outp, attp);
}

// round 12
// speedup vs baseline: 1.0290x; 1.0290x over previous
#include <cuda_runtime.h>
#include <cstdint>

// Fixed shapes: B=2048, L=200, D=128, A=64
#define DD 128
#define AA 64
#define LL 200
#define NEGINF (-4294967295.0f)
#define FNEGINF __int_as_float(0xff800000)

typedef unsigned long long ull;

__device__ __forceinline__ ull pk2(float lo, float hi) {
    ull r; asm("mov.b64 %0,{%1,%2};" : "=l"(r) : "f"(lo), "f"(hi)); return r;
}
__device__ __forceinline__ void upk2(ull v, float& lo, float& hi) {
    asm("mov.b64 {%0,%1},%2;" : "=f"(lo), "=f"(hi) : "l"(v));
}
__device__ __forceinline__ ull ffma2(ull a, ull b, ull c) {
    ull d; asm("fma.rn.f32x2 %0,%1,%2,%3;" : "=l"(d) : "l"(a), "l"(b), "l"(c)); return d;
}

// ---- kernel1 smem layout (float offsets) ----
#define F_KS   0          // K half [100][128] XOR-swizzled (12800 fl); after GEMM1
                          // reused as h1t [100][76] (7600 fl)
#define F_WC   12800      // Wc [128][64] natural       8192
#define F_W2   20992      // W2 [64][64] natural        4096
#define F_QS   25088      // q[128]
#define F_QC   25216      // qc[64]  (16B aligned)
#define F_B2   25280      // b2[64]
#define F_W3   25344      // W3[64]
#define F_QCP  25408      // qc partials [8][64]
#define K1_FLOATS 25920
#define K1_BYTES (K1_FLOATS * 4)    // 103680 B -> 2 CTAs/SM
#define H1S 76            // h1t row stride in floats (304 B = 19 granules)

// =================== Kernel 1: scores for one (batch, l-half) ===================
extern "C" __global__ void __launch_bounds__(512, 2)
din_scores(const float* __restrict__ query,
           const float* __restrict__ keys,
           const int*   __restrict__ klen,
           const float* __restrict__ W1,
           const float* __restrict__ b1,
           const float* __restrict__ a1p,
           const float* __restrict__ W2,
           const float* __restrict__ b2,
           const float* __restrict__ a2p,
           const float* __restrict__ W3,
           const float* __restrict__ b3p,
           float* __restrict__ attp)     // raw masked scores out (B, L)
{
    extern __shared__ float sm[];
    float4* S4 = (float4*)sm;
    const int t    = threadIdx.x;
    const int bh   = blockIdx.x;
    const int b    = bh >> 1;
    const int rowbase = (bh & 1) * 100;
    const int lg   = t >> 3;               // 0..63, busy if < 50
    const int cg   = t & 7;
    const int lgc  = (lg < 50) ? lg : 49;  // clamp: idle threads stay in-bounds
    const int l0   = 2 * lgc;
    const int cA   = 4 * cg;
    const int cB   = 32 + 4 * cg;

    const float pa1 = a1p[0], pa2 = a2p[0], b3v = b3p[0];
    const int   len = klen[b];

    // ---- Setup 1 ----
    if (t < DD) sm[F_QS + t] = query[b * DD + t];
    else if (t < DD + AA) sm[F_W3 + (t - DD)] = W3[t - DD];
    else if (t < DD + 2 * AA) sm[F_B2 + (t - DD - AA)] = b2[t - DD - AA];
    __syncthreads();

    // ---- Setup 2: Wc, W2, K-half, qc ----
    for (int i = t; i < DD * AA; i += 512) {
        int d = i >> 6, c = i & 63;
        sm[F_WC + i] = W1[(DD + d) * AA + c] - W1[(2 * DD + d) * AA + c]
                     + sm[F_QS + d] * W1[(3 * DD + d) * AA + c];
    }
    for (int i = t; i < AA * AA; i += 512) sm[F_W2 + i] = W2[i];
    {   // K rows rowbase..+99, float4, granule-XOR by (row>>1)&3
        const float4* K4 = (const float4*)(keys + ((size_t)b * LL + rowbase) * DD);
        for (int i = t; i < 100 * DD / 4; i += 512) {
            int row = i >> 5, q4 = i & 31;
            S4[row * 32 + (q4 ^ ((row >> 1) & 3))] = K4[i];
        }
    }
    {   // qc[a] = b1[a] + sum_d q[d]*(W1a+W1c)[d][a]
        int a = t & 63, seg = t >> 6;
        float s = 0.f;
        #pragma unroll
        for (int d = seg * 16; d < seg * 16 + 16; d++)
            s += sm[F_QS + d] * (W1[d * AA + a] + W1[(2 * DD + d) * AA + a]);
        sm[F_QCP + seg * 64 + a] = s;
    }
    __syncthreads();
    if (t < AA) {
        float s = b1[t];
        #pragma unroll
        for (int g = 0; g < 8; g++) s += sm[F_QCP + g * 64 + t];
        sm[F_QC + t] = s;
    }
    __syncthreads();

    // ==== GEMM1: 2l x 8c per thread, full d reduction ====
    ull acc[2][4];
    {
        const ull* qa = (const ull*)(sm + F_QC + cA);
        const ull* qb = (const ull*)(sm + F_QC + cB);
        acc[0][0] = qa[0]; acc[0][1] = qa[1]; acc[0][2] = qb[0]; acc[0][3] = qb[1];
        acc[1][0] = qa[0]; acc[1][1] = qa[1]; acc[1][2] = qb[0]; acc[1][3] = qb[1];
    }
    const int lp = lgc & 3;
    #pragma unroll 1
    for (int d4 = 0; d4 < 32; d4++) {
        float4 kv0 = S4[l0 * 32 + (d4 ^ lp)];
        float4 kv1 = S4[(l0 + 1) * 32 + (d4 ^ lp)];
        #pragma unroll
        for (int dd = 0; dd < 4; dd++) {
            const float* wrow = sm + F_WC + (d4 * 4 + dd) * 64;
            ulonglong2 wa = *(const ulonglong2*)(wrow + cA);
            ulonglong2 wb = *(const ulonglong2*)(wrow + cB);
            float kd0 = (dd == 0) ? kv0.x : (dd == 1) ? kv0.y : (dd == 2) ? kv0.z : kv0.w;
            float kd1 = (dd == 0) ? kv1.x : (dd == 1) ? kv1.y : (dd == 2) ? kv1.z : kv1.w;
            ull k0 = pk2(kd0, kd0), k1 = pk2(kd1, kd1);
            acc[0][0] = ffma2(k0, wa.x, acc[0][0]);
            acc[0][1] = ffma2(k0, wa.y, acc[0][1]);
            acc[0][2] = ffma2(k0, wb.x, acc[0][2]);
            acc[0][3] = ffma2(k0, wb.y, acc[0][3]);
            acc[1][0] = ffma2(k1, wa.x, acc[1][0]);
            acc[1][1] = ffma2(k1, wa.y, acc[1][1]);
            acc[1][2] = ffma2(k1, wb.x, acc[1][2]);
            acc[1][3] = ffma2(k1, wb.y, acc[1][3]);
        }
    }
    // prelu(a1) into hv[li][j]: j0..3 -> cA+j, j4..7 -> cB+(j-4)
    float hv[2][8];
    #pragma unroll
    for (int li = 0; li < 2; li++) {
        #pragma unroll
        for (int p = 0; p < 4; p++) {
            float lo, hi; upk2(acc[li][p], lo, hi);
            hv[li][2 * p]     = (lo >= 0.f) ? lo : pa1 * lo;
            hv[li][2 * p + 1] = (hi >= 0.f) ? hi : pa1 * hi;
        }
    }
    __syncthreads();   // all K reads complete; K region now reusable

    // ---- store h1t [l][a], stride 76 floats, into dead K area ----
    if (lg < 50) {
        #pragma unroll
        for (int li = 0; li < 2; li++) {
            *(float4*)(sm + F_KS + (l0 + li) * H1S + cA) =
                make_float4(hv[li][0], hv[li][1], hv[li][2], hv[li][3]);
            *(float4*)(sm + F_KS + (l0 + li) * H1S + cB) =
                make_float4(hv[li][4], hv[li][5], hv[li][6], hv[li][7]);
        }
    }
    __syncthreads();

    // ==== GEMM2: h2[l][c] = b2[c] + sum_a h1[l][a]*W2[a][c], 2l x 8c ====
    ull acc2[2][4];
    {
        const ull* ba = (const ull*)(sm + F_B2 + cA);
        const ull* bb = (const ull*)(sm + F_B2 + cB);
        acc2[0][0] = ba[0]; acc2[0][1] = ba[1]; acc2[0][2] = bb[0]; acc2[0][3] = bb[1];
        acc2[1][0] = ba[0]; acc2[1][1] = ba[1]; acc2[1][2] = bb[0]; acc2[1][3] = bb[1];
    }
    #pragma unroll 1
    for (int g = 0; g < 16; g++) {      // 4 a's per group
        float4 h0 = *(const float4*)(sm + F_KS + l0 * H1S + 4 * g);
        float4 h1 = *(const float4*)(sm + F_KS + (l0 + 1) * H1S + 4 * g);
        #pragma unroll
        for (int aa = 0; aa < 4; aa++) {
            const float* wrow = sm + F_W2 + (4 * g + aa) * 64;
            ulonglong2 wa = *(const ulonglong2*)(wrow + cA);
            ulonglong2 wb = *(const ulonglong2*)(wrow + cB);
            float hd0 = (aa == 0) ? h0.x : (aa == 1) ? h0.y : (aa == 2) ? h0.z : h0.w;
            float hd1 = (aa == 0) ? h1.x : (aa == 1) ? h1.y : (aa == 2) ? h1.z : h1.w;
            ull k0 = pk2(hd0, hd0), k1 = pk2(hd1, hd1);
            acc2[0][0] = ffma2(k0, wa.x, acc2[0][0]);
            acc2[0][1] = ffma2(k0, wa.y, acc2[0][1]);
            acc2[0][2] = ffma2(k0, wb.x, acc2[0][2]);
            acc2[0][3] = ffma2(k0, wb.y, acc2[0][3]);
            acc2[1][0] = ffma2(k1, wa.x, acc2[1][0]);
            acc2[1][1] = ffma2(k1, wa.y, acc2[1][1]);
            acc2[1][2] = ffma2(k1, wb.x, acc2[1][2]);
            acc2[1][3] = ffma2(k1, wb.y, acc2[1][3]);
        }
    }

    // prelu(a2) + W3 dot -> 2 partial scores, reduce over cg lanes
    float w3a[4], w3b[4];
    #pragma unroll
    for (int p = 0; p < 4; p++) { w3a[p] = sm[F_W3 + cA + p]; w3b[p] = sm[F_W3 + cB + p]; }
    float s0 = 0.f, s1 = 0.f;
    #pragma unroll
    for (int li = 0; li < 2; li++) {
        float s = 0.f, lo, hi;
        upk2(acc2[li][0], lo, hi);
        lo = (lo >= 0.f) ? lo : pa2 * lo;  hi = (hi >= 0.f) ? hi : pa2 * hi;
        s += lo * w3a[0] + hi * w3a[1];
        upk2(acc2[li][1], lo, hi);
        lo = (lo >= 0.f) ? lo : pa2 * lo;  hi = (hi >= 0.f) ? hi : pa2 * hi;
        s += lo * w3a[2] + hi * w3a[3];
        upk2(acc2[li][2], lo, hi);
        lo = (lo >= 0.f) ? lo : pa2 * lo;  hi = (hi >= 0.f) ? hi : pa2 * hi;
        s += lo * w3b[0] + hi * w3b[1];
        upk2(acc2[li][3], lo, hi);
        lo = (lo >= 0.f) ? lo : pa2 * lo;  hi = (hi >= 0.f) ? hi : pa2 * hi;
        s += lo * w3b[2] + hi * w3b[3];
        if (li == 0) s0 = s; else s1 = s;
    }
    #pragma unroll
    for (int o = 4; o > 0; o >>= 1) {
        s0 += __shfl_xor_sync(0xffffffffu, s0, o);
        s1 += __shfl_xor_sync(0xffffffffu, s1, o);
    }
    if (lg < 50 && cg == 0) {
        int l = rowbase + l0;
        attp[(size_t)b * LL + l]     = (l < len)     ? (s0 + b3v) : NEGINF;
        attp[(size_t)b * LL + l + 1] = (l + 1 < len) ? (s1 + b3v) : NEGINF;
    }
}

// =================== Kernel 2: softmax + out = att @ K ===================
extern "C" __global__ void __launch_bounds__(256)
din_softmax_out(const float* __restrict__ keys,
                float* __restrict__ outp,
                float* __restrict__ attp)
{
    __shared__ float sc[256];
    __shared__ float red[32];
    __shared__ float part[256];
    const int t = threadIdx.x;
    const int b = blockIdx.x;
    const int lane = t & 31, w = t >> 5;

    sc[t] = (t < LL) ? attp[(size_t)b * LL + t] : FNEGINF;
    __syncthreads();

    float v = sc[t];
    float m = v;
    #pragma unroll
    for (int o = 16; o > 0; o >>= 1) m = fmaxf(m, __shfl_xor_sync(0xffffffffu, m, o));
    if (lane == 0) red[w] = m;
    __syncthreads();
    if (t == 0) {
        float mm = red[0];
        for (int i = 1; i < 8; i++) mm = fmaxf(mm, red[i]);
        red[8] = mm;
    }
    __syncthreads();
    float M = red[8];
    float e = (t < LL) ? __expf(v - M) : 0.f;
    float ss = e;
    #pragma unroll
    for (int o = 16; o > 0; o >>= 1) ss += __shfl_xor_sync(0xffffffffu, ss, o);
    if (lane == 0) red[16 + w] = ss;
    __syncthreads();
    if (t == 0) {
        float s = 0.f;
        for (int i = 0; i < 8; i++) s += red[16 + i];
        red[24] = s;
    }
    __syncthreads();
    float at = 0.f;
    if (t < LL) {
        at = e / red[24];
        attp[(size_t)b * LL + t] = at;
    }
    __syncthreads();
    sc[t] = at;
    __syncthreads();

    {   // out[b][d] = sum_l att[l]*K[l][d]; 2-way l split, coalesced LDG
        int d = t & 127, seg = t >> 7;
        const float* Kb = keys + ((size_t)b * LL + seg * 100) * DD + d;
        const float* Ap = sc + seg * 100;
        float a0 = 0.f, a1 = 0.f;
        #pragma unroll 4
        for (int l = 0; l < 100; l += 2) {
            a0 += Ap[l]     * Kb[l * DD];
            a1 += Ap[l + 1] * Kb[(l + 1) * DD];
        }
        part[t] = a0 + a1;
    }
    __syncthreads();
    if (t < DD) outp[(size_t)b * DD + t] = part[t] + part[t + 128];
}

extern "C" void kernel_launch(void* const* d_in, const int* in_sizes, int n_in,
                              void* d_out, int out_size) {
    const float* query = (const float*)d_in[0];
    const float* keys  = (const float*)d_in[1];
    const int*   klen  = (const int*)  d_in[2];
    const float* W1    = (const float*)d_in[3];
    const float* b1    = (const float*)d_in[4];
    const float* a1    = (const float*)d_in[5];
    const float* W2    = (const float*)d_in[6];
    const float* b2    = (const float*)d_in[7];
    const float* a2    = (const float*)d_in[8];
    const float* W3    = (const float*)d_in[9];
    const float* b3    = (const float*)d_in[10];

    int Bn = in_sizes[0] / DD;  // 2048
    float* outp = (float*)d_out;               // (B, D)
    float* attp = outp + (size_t)Bn * DD;      // (B, L)

    cudaFuncSetAttribute(din_scores,
                         cudaFuncAttributeMaxDynamicSharedMemorySize, K1_BYTES);
    din_scores<<<2 * Bn, 512, K1_BYTES>>>(
        query, keys, klen, W1, b1, a1, W2, b2, a2, W3, b3, attp);
    din_softmax_out<<<Bn, 256>>>(keys, outp, attp);
}

// round 13
// speedup vs baseline: 1.1958x; 1.1621x over previous
#include <cuda_runtime.h>
#include <cstdint>

// Fixed shapes: B=2048, L=200, D=128, A=64
#define DD 128
#define AA 64
#define LL 200
#define BB 2048
#define NEGINF (-4294967295.0f)
#define FNEGINF __int_as_float(0xff800000)

typedef unsigned long long ull;

__device__ __forceinline__ ull pk2(float lo, float hi) {
    ull r; asm("mov.b64 %0,{%1,%2};" : "=l"(r) : "f"(lo), "f"(hi)); return r;
}
__device__ __forceinline__ void upk2(ull v, float& lo, float& hi) {
    asm("mov.b64 {%0,%1},%2;" : "=f"(lo), "=f"(hi) : "l"(v));
}
__device__ __forceinline__ ull ffma2(ull a, ull b, ull c) {
    ull d; asm("fma.rn.f32x2 %0,%1,%2,%3;" : "=l"(d) : "l"(a), "l"(b), "l"(c)); return d;
}

// ---- device scratch (module-load allocation; no runtime alloc) ----
__device__ ull   g_Wcd[(size_t)BB * 4096];   // per-batch d-pair-interleaved Wc
__device__ float g_qc[(size_t)BB * 64];      // per-batch qc (b1 + q-part)
__device__ ull   g_W2d[2048];                // d-pair-interleaved W2 (global)

// ---- kernel1 smem layout (float offsets) ----
#define F_KS   0          // K [200][128] XOR-swizzled (25600 fl)
#define F_WCD  25600      // Wcd [64][64] ull = 8192 fl
#define F_W2D  33792      // W2d [32][64] ull = 4096 fl
#define F_H1   37888      // h1 [200][68] fl = 13600
#define F_QC   51488      // qc[64]
#define F_B2   51552      // b2[64]
#define F_W3   51616      // W3[64]
#define F_SC   51680      // scores/att [256]
#define F_RED  51936      // softmax scratch [32]
#define F_OUT  51968      // out partials [4][128]
#define SMEM_FLOATS 52480
#define SMEM_BYTES  (SMEM_FLOATS * 4)   // 209920 B -> 1 CTA/SM
#define H1S 68            // h1 row stride (floats)

// =============== prep kernel A: W2 pair-interleave (grid 1) ===============
extern "C" __global__ void __launch_bounds__(256)
din_prep_w2(const float* __restrict__ W2) {
    for (int i = threadIdx.x; i < 2048; i += 256) {
        int e = i >> 6, c = i & 63;
        g_W2d[i] = pk2(W2[(2 * e) * AA + c], W2[(2 * e + 1) * AA + c]);
    }
}

// =============== prep kernel B: per-batch Wcd + qc (grid B) ===============
extern "C" __global__ void __launch_bounds__(256)
din_prep(const float* __restrict__ query,
         const float* __restrict__ W1,
         const float* __restrict__ b1) {
    __shared__ float q[DD];
    __shared__ float qp[4][64];
    const int t = threadIdx.x;
    const int b = blockIdx.x;
    if (t < DD) q[t] = query[b * DD + t];
    __syncthreads();

    ull* out = g_Wcd + (size_t)b * 4096;
    for (int i = t; i < 4096; i += 256) {
        int e = i >> 6, c = i & 63;
        int d0 = 2 * e, d1 = 2 * e + 1;
        float we = W1[(DD + d0) * AA + c] - W1[(2 * DD + d0) * AA + c]
                 + q[d0] * W1[(3 * DD + d0) * AA + c];
        float wo = W1[(DD + d1) * AA + c] - W1[(2 * DD + d1) * AA + c]
                 + q[d1] * W1[(3 * DD + d1) * AA + c];
        out[i] = pk2(we, wo);
    }
    {   // qc[a] = b1[a] + sum_d q[d]*(W1a+W1c)[d][a]
        int a = t & 63, seg = t >> 6;
        float s = 0.f;
        for (int d = seg * 32; d < seg * 32 + 32; d++)
            s += q[d] * (W1[d * AA + a] + W1[(2 * DD + d) * AA + a]);
        qp[seg][a] = s;
    }
    __syncthreads();
    if (t < 64)
        g_qc[(size_t)b * 64 + t] = b1[t] + qp[0][t] + qp[1][t] + qp[2][t] + qp[3][t];
}

// =============== main fused kernel (grid B, 512 thr) ===============
extern "C" __global__ void __launch_bounds__(512)
din_main(const float* __restrict__ keys,
         const int*   __restrict__ klen,
         const float* __restrict__ b2,
         const float* __restrict__ a1p,
         const float* __restrict__ a2p,
         const float* __restrict__ W3,
         const float* __restrict__ b3p,
         float* __restrict__ outp,
         float* __restrict__ attp)
{
    extern __shared__ float sm[];
    float4* S4 = (float4*)sm;
    ull* wcd = (ull*)(sm + F_WCD);
    ull* w2d = (ull*)(sm + F_W2D);
    const int t    = threadIdx.x;
    const int b    = blockIdx.x;
    const int lg   = t >> 3;               // 0..63, busy if < 50
    const int cg   = t & 7;
    const int lgc  = (lg < 50) ? lg : 49;
    const int l0   = 4 * lgc;
    const int lane = t & 31;
    const int w    = t >> 5;

    const float pa1 = a1p[0], pa2 = a2p[0], b3v = b3p[0];
    const int   len = klen[b];

    // ---- setup: stream Wcd, W2d, qc; copy K with XOR swizzle; b2/W3 ----
    {
        const ulonglong2* Wg = (const ulonglong2*)(g_Wcd + (size_t)b * 4096);
        ulonglong2* Ws = (ulonglong2*)wcd;
        for (int i = t; i < 2048; i += 512) Ws[i] = Wg[i];
        const ulonglong2* W2g = (const ulonglong2*)g_W2d;
        ulonglong2* W2s = (ulonglong2*)w2d;
        for (int i = t; i < 1024; i += 512) W2s[i] = W2g[i];
        const float4* K4 = (const float4*)(keys + (size_t)b * LL * DD);
        for (int i = t; i < LL * DD / 4; i += 512) {
            int row = i >> 5, q4 = i & 31;
            S4[row * 32 + (q4 ^ ((row >> 2) & 3))] = K4[i];
        }
        if (t < 64) sm[F_QC + t] = g_qc[(size_t)b * 64 + t];
        else if (t < 128) sm[F_B2 + (t - 64)] = b2[t - 64];
        else if (t < 192) sm[F_W3 + (t - 128)] = W3[t - 128];
    }
    __syncthreads();

    // ==== GEMM1: acc[li][2k+j] = (even-d, odd-d) partials for c = 16k+2cg+j ====
    float s0 = 0.f, s1 = 0.f, s2 = 0.f, s3 = 0.f;  // score partials
    {
        ull acc[4][8];
        #pragma unroll
        for (int li = 0; li < 4; li++)
            #pragma unroll
            for (int j = 0; j < 8; j++) acc[li][j] = 0ULL;

        const int lp = lgc & 3;
        if (lg < 50) {
            #pragma unroll 1
            for (int q4 = 0; q4 < 32; q4++) {
                float4 kv0 = S4[l0 * 32 + (q4 ^ lp)];
                float4 kv1 = S4[(l0 + 1) * 32 + (q4 ^ lp)];
                float4 kv2 = S4[(l0 + 2) * 32 + (q4 ^ lp)];
                float4 kv3 = S4[(l0 + 3) * 32 + (q4 ^ lp)];
                #pragma unroll
                for (int p = 0; p < 2; p++) {
                    const ull* wr = wcd + (2 * q4 + p) * 64 + 2 * cg;
                    ull kp0 = p ? pk2(kv0.z, kv0.w) : pk2(kv0.x, kv0.y);
                    ull kp1 = p ? pk2(kv1.z, kv1.w) : pk2(kv1.x, kv1.y);
                    ull kp2 = p ? pk2(kv2.z, kv2.w) : pk2(kv2.x, kv2.y);
                    ull kp3 = p ? pk2(kv3.z, kv3.w) : pk2(kv3.x, kv3.y);
                    #pragma unroll
                    for (int k = 0; k < 4; k++) {
                        ulonglong2 wv = *(const ulonglong2*)(wr + 16 * k);
                        acc[0][2*k]   = ffma2(kp0, wv.x, acc[0][2*k]);
                        acc[0][2*k+1] = ffma2(kp0, wv.y, acc[0][2*k+1]);
                        acc[1][2*k]   = ffma2(kp1, wv.x, acc[1][2*k]);
                        acc[1][2*k+1] = ffma2(kp1, wv.y, acc[1][2*k+1]);
                        acc[2][2*k]   = ffma2(kp2, wv.x, acc[2][2*k]);
                        acc[2][2*k+1] = ffma2(kp2, wv.y, acc[2][2*k+1]);
                        acc[3][2*k]   = ffma2(kp3, wv.x, acc[3][2*k]);
                        acc[3][2*k+1] = ffma2(kp3, wv.y, acc[3][2*k+1]);
                    }
                }
            }
        }
        __syncthreads();   // K reads done (region stays live for epilogue)

        // finalize h1 = lo+hi+qc, prelu, store pairs to h1[l][c]
        if (lg < 50) {
            float2 qp2[4];
            #pragma unroll
            for (int k = 0; k < 4; k++)
                qp2[k] = *(const float2*)(sm + F_QC + 16 * k + 2 * cg);
            #pragma unroll
            for (int li = 0; li < 4; li++) {
                #pragma unroll
                for (int k = 0; k < 4; k++) {
                    float lo, hi, h0, h1;
                    upk2(acc[li][2*k], lo, hi);     h0 = lo + hi + qp2[k].x;
                    upk2(acc[li][2*k+1], lo, hi);   h1 = lo + hi + qp2[k].y;
                    h0 = (h0 >= 0.f) ? h0 : pa1 * h0;
                    h1 = (h1 >= 0.f) ? h1 : pa1 * h1;
                    *(float2*)(sm + F_H1 + (l0 + li) * H1S + 16 * k + 2 * cg) =
                        make_float2(h0, h1);
                }
            }
        }
    }
    __syncthreads();

    // ==== GEMM2: same d-parity trick over a (32 a-pairs) ====
    {
        ull acc[4][8];
        #pragma unroll
        for (int li = 0; li < 4; li++)
            #pragma unroll
            for (int j = 0; j < 8; j++) acc[li][j] = 0ULL;

        if (lg < 50) {
            #pragma unroll 1
            for (int m = 0; m < 16; m++) {     // float4 = a 4m..4m+3 = pairs 2m,2m+1
                float4 h0 = *(const float4*)(sm + F_H1 + l0 * H1S + 4 * m);
                float4 h1 = *(const float4*)(sm + F_H1 + (l0 + 1) * H1S + 4 * m);
                float4 h2 = *(const float4*)(sm + F_H1 + (l0 + 2) * H1S + 4 * m);
                float4 h3 = *(const float4*)(sm + F_H1 + (l0 + 3) * H1S + 4 * m);
                #pragma unroll
                for (int p = 0; p < 2; p++) {
                    const ull* wr = w2d + (2 * m + p) * 64 + 2 * cg;
                    ull hp0 = p ? pk2(h0.z, h0.w) : pk2(h0.x, h0.y);
                    ull hp1 = p ? pk2(h1.z, h1.w) : pk2(h1.x, h1.y);
                    ull hp2 = p ? pk2(h2.z, h2.w) : pk2(h2.x, h2.y);
                    ull hp3 = p ? pk2(h3.z, h3.w) : pk2(h3.x, h3.y);
                    #pragma unroll
                    for (int k = 0; k < 4; k++) {
                        ulonglong2 wv = *(const ulonglong2*)(wr + 16 * k);
                        acc[0][2*k]   = ffma2(hp0, wv.x, acc[0][2*k]);
                        acc[0][2*k+1] = ffma2(hp0, wv.y, acc[0][2*k+1]);
                        acc[1][2*k]   = ffma2(hp1, wv.x, acc[1][2*k]);
                        acc[1][2*k+1] = ffma2(hp1, wv.y, acc[1][2*k+1]);
                        acc[2][2*k]   = ffma2(hp2, wv.x, acc[2][2*k]);
                        acc[2][2*k+1] = ffma2(hp2, wv.y, acc[2][2*k+1]);
                        acc[3][2*k]   = ffma2(hp3, wv.x, acc[3][2*k]);
                        acc[3][2*k+1] = ffma2(hp3, wv.y, acc[3][2*k+1]);
                    }
                }
            }
            // h2 = lo+hi+b2, prelu(a2), dot W3 -> 4 score partials
            float2 b2p[4], w3p[4];
            #pragma unroll
            for (int k = 0; k < 4; k++) {
                b2p[k] = *(const float2*)(sm + F_B2 + 16 * k + 2 * cg);
                w3p[k] = *(const float2*)(sm + F_W3 + 16 * k + 2 * cg);
            }
            float ps[4];
            #pragma unroll
            for (int li = 0; li < 4; li++) {
                float s = 0.f;
                #pragma unroll
                for (int k = 0; k < 4; k++) {
                    float lo, hi, v0, v1;
                    upk2(acc[li][2*k], lo, hi);   v0 = lo + hi + b2p[k].x;
                    upk2(acc[li][2*k+1], lo, hi); v1 = lo + hi + b2p[k].y;
                    v0 = (v0 >= 0.f) ? v0 : pa2 * v0;
                    v1 = (v1 >= 0.f) ? v1 : pa2 * v1;
                    s += v0 * w3p[k].x + v1 * w3p[k].y;
                }
                ps[li] = s;
            }
            s0 = ps[0]; s1 = ps[1]; s2 = ps[2]; s3 = ps[3];
        }
    }
    #pragma unroll
    for (int o = 4; o > 0; o >>= 1) {
        s0 += __shfl_xor_sync(0xffffffffu, s0, o);
        s1 += __shfl_xor_sync(0xffffffffu, s1, o);
        s2 += __shfl_xor_sync(0xffffffffu, s2, o);
        s3 += __shfl_xor_sync(0xffffffffu, s3, o);
    }
    if (lg < 50 && cg == 0) {
        float sc[4] = {s0, s1, s2, s3};
        #pragma unroll
        for (int li = 0; li < 4; li++) {
            int l = l0 + li;
            sm[F_SC + l] = (l < len) ? (sc[li] + b3v) : NEGINF;
        }
    }
    if (t >= 400 && t < 456) sm[F_SC + (t - 200)] = FNEGINF;
    __syncthreads();

    // ---- softmax over 256 slots ----
    float v = 0.f, e = 0.f;
    if (t < 256) {
        v = sm[F_SC + t];
        float m = v;
        #pragma unroll
        for (int o = 16; o > 0; o >>= 1) m = fmaxf(m, __shfl_xor_sync(0xffffffffu, m, o));
        if (lane == 0) sm[F_RED + w] = m;
    }
    __syncthreads();
    if (t == 0) {
        float mm = sm[F_RED];
        for (int i = 1; i < 8; i++) mm = fmaxf(mm, sm[F_RED + i]);
        sm[F_RED + 8] = mm;
    }
    __syncthreads();
    if (t < 256) {
        float M = sm[F_RED + 8];
        e = (t < LL) ? __expf(v - M) : 0.f;
        float ss = e;
        #pragma unroll
        for (int o = 16; o > 0; o >>= 1) ss += __shfl_xor_sync(0xffffffffu, ss, o);
        if (lane == 0) sm[F_RED + 16 + w] = ss;
    }
    __syncthreads();
    if (t == 0) {
        float s = 0.f;
        for (int i = 0; i < 8; i++) s += sm[F_RED + 16 + i];
        sm[F_RED + 24] = s;
    }
    __syncthreads();
    if (t < LL) {
        float at = e / sm[F_RED + 24];
        sm[F_SC + t] = at;
        attp[(size_t)b * LL + t] = at;
    }
    __syncthreads();

    // ---- out[b][d] = sum_l att[l]*K[l][d], 4-way l split (swizzled K read) ----
    {
        int d = t & 127, seg = t >> 7;
        int q4 = d >> 2, dc = d & 3;
        float a0 = 0.f, a1 = 0.f;
        const float* Ap = sm + F_SC + seg * 50;
        #pragma unroll 5
        for (int l2 = 0; l2 < 50; l2 += 2) {
            int la = seg * 50 + l2, lb = la + 1;
            float ka = sm[la * 128 + (q4 ^ ((la >> 2) & 3)) * 4 + dc];
            float kb = sm[lb * 128 + (q4 ^ ((lb >> 2) & 3)) * 4 + dc];
            a0 += Ap[l2] * ka;
            a1 += Ap[l2 + 1] * kb;
        }
        sm[F_OUT + seg * 128 + d] = a0 + a1;
    }
    __syncthreads();
    if (t < DD) {
        outp[(size_t)b * DD + t] = (sm[F_OUT + t] + sm[F_OUT + 128 + t])
                                 + (sm[F_OUT + 256 + t] + sm[F_OUT + 384 + t]);
    }
}

extern "C" void kernel_launch(void* const* d_in, const int* in_sizes, int n_in,
                              void* d_out, int out_size) {
    const float* query = (const float*)d_in[0];
    const float* keys  = (const float*)d_in[1];
    const int*   klen  = (const int*)  d_in[2];
    const float* W1    = (const float*)d_in[3];
    const float* b1    = (const float*)d_in[4];
    const float* a1    = (const float*)d_in[5];
    const float* W2    = (const float*)d_in[6];
    const float* b2    = (const float*)d_in[7];
    const float* a2    = (const float*)d_in[8];
    const float* W3    = (const float*)d_in[9];
    const float* b3    = (const float*)d_in[10];

    int Bn = in_sizes[0] / DD;  // 2048
    float* outp = (float*)d_out;               // (B, D)
    float* attp = outp + (size_t)Bn * DD;      // (B, L)

    din_prep_w2<<<1, 256>>>(W2);
    din_prep<<<Bn, 256>>>(query, W1, b1);
    cudaFuncSetAttribute(din_main,
                         cudaFuncAttributeMaxDynamicSharedMemorySize, SMEM_BYTES);
    din_main<<<Bn, 512, SMEM_BYTES>>>(
        keys, klen, b2, a1, a2, W3, b3, outp, attp);
}